// round 6
// baseline (speedup 1.0000x reference)
#include <cuda_runtime.h>
#include <math.h>
#include <stdint.h>

#define N 8192
#define CLS 8
#define DIM 256
#define INV_T 14.285714285714286f
#define EXP_SCALE 20.60992915555662f   /* (1/0.07) * log2(e) */
#define ALPHA 0.3f
#define LSM 0.1f
#define NT_ROW 64

// ---------------- scratch ------------------------------------------------------------
__device__ float g_embn[N * DIM];
__device__ uint16_t g_embq[N * DIM / 2];     // e4m3 pairs (256 B/row)
__device__ float g_clsum_part[32 * CLS * DIM];
__device__ float g_clcnt_part[32 * CLS];
__device__ float g_clsum[CLS * DIM];
__device__ float g_clcnt[CLS];
__device__ float g_Zp[N * NT_ROW];
__device__ float g_con[N];
__device__ float g_ce_part[32];

// ---------------- helpers ------------------------------------------------------------
__device__ __forceinline__ uint32_t smem_u32(const void* p) {
    uint32_t a;
    asm("{ .reg .u64 t; cvta.to.shared.u64 t, %1; cvt.u32.u64 %0, t; }" : "=r"(a) : "l"(p));
    return a;
}
__device__ __forceinline__ float ex2f(float x) {
    float y; asm("ex2.approx.f32 %0, %1;" : "=f"(y) : "f"(x)); return y;
}
__device__ __forceinline__ void cp16(uint32_t dst, const void* src) {
    asm volatile("cp.async.cg.shared.global [%0], [%1], 16;" :: "r"(dst), "l"(src));
}
#define CP_COMMIT() asm volatile("cp.async.commit_group;" ::: "memory")
#define CP_WAIT0()  asm volatile("cp.async.wait_group 0;" ::: "memory")

__device__ __forceinline__ void ldsm4(uint32_t& r0, uint32_t& r1, uint32_t& r2, uint32_t& r3,
                                      uint32_t addr) {
    asm volatile("ldmatrix.sync.aligned.m8n8.x4.shared.b16 {%0,%1,%2,%3}, [%4];"
                 : "=r"(r0), "=r"(r1), "=r"(r2), "=r"(r3) : "r"(addr));
}
// FP8 e4m3, K=32, fp32 accumulate
__device__ __forceinline__ void mma_fp8(float* c, uint32_t a0, uint32_t a1, uint32_t a2,
                                        uint32_t a3, uint32_t b0, uint32_t b1) {
    asm volatile("mma.sync.aligned.m16n8k32.row.col.f32.e4m3.e4m3.f32 "
                 "{%0,%1,%2,%3}, {%4,%5,%6,%7}, {%8,%9}, {%0,%1,%2,%3};"
                 : "+f"(c[0]), "+f"(c[1]), "+f"(c[2]), "+f"(c[3])
                 : "r"(a0), "r"(a1), "r"(a2), "r"(a3), "r"(b0), "r"(b1));
}
__device__ __forceinline__ uint16_t f2e4m3x2(float hi, float lo) {
    uint16_t r;
    asm("cvt.rn.satfinite.e4m3x2.f32 %0, %1, %2;" : "=h"(r) : "f"(hi), "f"(lo));
    return r;
}

// ---------------- 1) normalize + fp8 convert ----------------------------------------
__global__ void k_norm(const float* __restrict__ emb) {
    int row = blockIdx.x;
    int d = threadIdx.x;
    float v = emb[row * DIM + d];
    __shared__ float s[DIM];
    __shared__ float sv[DIM];
    s[d] = v * v;
    __syncthreads();
    for (int off = DIM / 2; off > 0; off >>= 1) {
        if (d < off) s[d] += s[d + off];
        __syncthreads();
    }
    float norm = fmaxf(sqrtf(s[0]), 1e-12f);
    float nv = v / norm;
    g_embn[row * DIM + d] = nv;
    sv[d] = nv;
    __syncthreads();
    if (d < DIM / 2) {
        g_embq[row * (DIM / 2) + d] = f2e4m3x2(sv[2 * d + 1], sv[2 * d]);
    }
}

// ---------------- 2) class sums ------------------------------------------------------
__global__ void k_clspart(const int* __restrict__ tgt) {
    int b = blockIdx.x, d = threadIdx.x;
    int i0 = b * 256;
    __shared__ int st[256];
    st[d] = tgt[i0 + d];
    __syncthreads();
    float a[CLS];
#pragma unroll
    for (int c = 0; c < CLS; c++) a[c] = 0.f;
    for (int k = 0; k < 256; k++) {
        float v = g_embn[(i0 + k) * DIM + d];
        int t = st[k];
#pragma unroll
        for (int c = 0; c < CLS; c++) a[c] += (t == c) ? v : 0.f;
    }
#pragma unroll
    for (int c = 0; c < CLS; c++) g_clsum_part[(b * CLS + c) * DIM + d] = a[c];
    if (d == 0) {
        int cnt[CLS];
#pragma unroll
        for (int c = 0; c < CLS; c++) cnt[c] = 0;
        for (int k = 0; k < 256; k++) {
#pragma unroll
            for (int c = 0; c < CLS; c++) cnt[c] += (st[k] == c);
        }
#pragma unroll
        for (int c = 0; c < CLS; c++) g_clcnt_part[b * CLS + c] = (float)cnt[c];
    }
}

__global__ void k_clsfinal() {
    int c = blockIdx.x, d = threadIdx.x;
    float s = 0.f;
    for (int b = 0; b < 32; b++) s += g_clsum_part[(b * CLS + c) * DIM + d];
    g_clsum[c * DIM + d] = s;
    if (d == 0) {
        float cn = 0.f;
        for (int b = 0; b < 32; b++) cn += g_clcnt_part[b * CLS + c];
        g_clcnt[c] = cn;
    }
}

// ---------------- 3) focal cross-entropy --------------------------------------------
__global__ void k_ce(const float* __restrict__ logits, const int* __restrict__ tgt) {
    int i = blockIdx.x * 256 + threadIdx.x;
    const float4* p = (const float4*)(logits + i * CLS);
    float4 u = p[0], w = p[1];
    float x[CLS] = {u.x, u.y, u.z, u.w, w.x, w.y, w.z, w.w};
    float m = x[0];
#pragma unroll
    for (int j = 1; j < CLS; j++) m = fmaxf(m, x[j]);
    float se = 0.f;
#pragma unroll
    for (int j = 0; j < CLS; j++) se += expf(x[j] - m);
    float lse = m + logf(se);
    int t = tgt[i];
    float nll = lse - x[t];
    float sx = 0.f;
#pragma unroll
    for (int j = 0; j < CLS; j++) sx += x[j];
    float smooth = lse - sx * (1.0f / CLS);
    float ce = (1.0f - LSM) * nll + LSM * smooth;
    float pt = expf(-ce);
    float omp = 1.0f - pt;
    float focal = omp * omp * ce;

    __shared__ float s[256];
    s[threadIdx.x] = focal;
    __syncthreads();
    for (int off = 128; off > 0; off >>= 1) {
        if (threadIdx.x < off) s[threadIdx.x] += s[threadIdx.x + off];
        __syncthreads();
    }
    if (threadIdx.x == 0) g_ce_part[blockIdx.x] = s[0];
}

// ---------------- 4) HOT: symmetric Z via mma.sync fp8 (K=32/instr) -----------------
#define SAB 272                          /* row stride in bytes (256 + 16 pad) */
#define A_BYTES (128 * SAB)              /* 34816 */
#define AS_OFF 0
#define BS_OFF(b) (A_BYTES + (b) * A_BYTES)
#define RED_OFF (3 * A_BYTES)            /* 104448 */
#define SMEM_TOTAL (RED_OFF + 128 * 2 * 4 + 128 * 4 * 4)

__device__ __forceinline__ void load_tile_async(uint32_t sbase, int grow0, int tid) {
    const char* src = (const char*)g_embq + (size_t)grow0 * 256;
#pragma unroll
    for (int i = 0; i < 8; i++) {
        int idx = tid + i * 256;
        int row = idx >> 4, cb = idx & 15;
        cp16(sbase + row * SAB + cb * 16, src + (size_t)row * 256 + cb * 16);
    }
}

__global__ void __launch_bounds__(256, 1) k_sim_sym() {
    extern __shared__ char smem[];
    uint32_t sb = smem_u32(smem);
    float* red_row = (float*)(smem + RED_OFF);          // [128][2]
    float* red_col = (float*)(smem + RED_OFF + 1024);   // [128][4]
    int tid = threadIdx.x;
    int lane = tid & 31;
    int wid = tid >> 5;
    int wx = wid & 1;
    int wy = wid >> 1;

    int rem = blockIdx.x * 16;
    int I = 0;
    while (rem >= NT_ROW - I) { rem -= NT_ROW - I; I++; }
    int J = I + rem;

    uint32_t a_addr = sb + AS_OFF + (wy * 32 + (lane & 15)) * SAB + ((lane >> 4) << 4);
    uint32_t b_addr = sb + ((lane & 7) + ((lane >> 4) << 3)) * SAB + (((lane >> 3) & 1) << 4);
    uint32_t b_base = b_addr + (wx * 64) * SAB;

    const float EXP_DIAG = expf(INV_T);
    int lrl0 = wy * 32 + (lane >> 2);
    int lcb0 = wx * 64 + (lane & 3) * 2;

    int curI = -1;

    for (int k = 0; k < 16; k++) {
        int buf = k & 1;
        if (I != curI) {
            load_tile_async(sb + AS_OFF, I * 128, tid);
            if (k == 0) load_tile_async(sb + BS_OFF(0), J * 128, tid);
            CP_COMMIT();
            CP_WAIT0();
            __syncthreads();
            curI = I;
        }
        int I1 = I, J1 = J + 1;
        if (J1 == NT_ROW) { I1 = I + 1; J1 = I1; }
        if (k + 1 < 16) {
            load_tile_async(sb + BS_OFF(buf ^ 1), J1 * 128, tid);
            CP_COMMIT();
        }

        // ---- MMA: 128x128x256 in 8 K-steps of 32 ----
        float acc[2][8][4];
#pragma unroll
        for (int mt = 0; mt < 2; mt++)
#pragma unroll
            for (int nt = 0; nt < 8; nt++)
#pragma unroll
                for (int q = 0; q < 4; q++) acc[mt][nt][q] = 0.f;

        uint32_t bbuf = b_base + BS_OFF(buf);
#pragma unroll
        for (int ks = 0; ks < 8; ks++) {
            uint32_t koff = ks * 32;
            uint32_t a0[4], a1[4];
            ldsm4(a0[0], a0[1], a0[2], a0[3], a_addr + koff);
            ldsm4(a1[0], a1[1], a1[2], a1[3], a_addr + 16 * SAB + koff);
            uint32_t bfr[4][4];
#pragma unroll
            for (int p = 0; p < 4; p++)
                ldsm4(bfr[p][0], bfr[p][1], bfr[p][2], bfr[p][3],
                      bbuf + (p * 16) * SAB + koff);
#pragma unroll
            for (int nt = 0; nt < 8; nt++) {
                uint32_t bb0 = bfr[nt >> 1][(nt & 1) * 2];
                uint32_t bb1 = bfr[nt >> 1][(nt & 1) * 2 + 1];
                mma_fp8(acc[0][nt], a0[0], a0[1], a0[2], a0[3], bb0, bb1);
                mma_fp8(acc[1][nt], a1[0], a1[1], a1[2], a1[3], bb0, bb1);
            }
        }

        // ---- epilogue ----
        bool dt = (I == J);
        float ev[2][8][4];
#pragma unroll
        for (int mt = 0; mt < 2; mt++) {
            int lr = lrl0 + mt * 16;
#pragma unroll
            for (int nt = 0; nt < 8; nt++) {
                int lc = lcb0 + nt * 8;
                ev[mt][nt][0] = (dt && lc == lr)         ? EXP_DIAG : ex2f(acc[mt][nt][0] * EXP_SCALE);
                ev[mt][nt][1] = (dt && lc + 1 == lr)     ? EXP_DIAG : ex2f(acc[mt][nt][1] * EXP_SCALE);
                ev[mt][nt][2] = (dt && lc == lr + 8)     ? EXP_DIAG : ex2f(acc[mt][nt][2] * EXP_SCALE);
                ev[mt][nt][3] = (dt && lc + 1 == lr + 8) ? EXP_DIAG : ex2f(acc[mt][nt][3] * EXP_SCALE);
            }
        }

        // row sums
        float rlo[2], rhi[2];
#pragma unroll
        for (int mt = 0; mt < 2; mt++) {
            float sl = 0.f, sh = 0.f;
#pragma unroll
            for (int nt = 0; nt < 8; nt++) {
                sl += ev[mt][nt][0] + ev[mt][nt][1];
                sh += ev[mt][nt][2] + ev[mt][nt][3];
            }
            sl += __shfl_xor_sync(0xFFFFFFFF, sl, 1);
            sl += __shfl_xor_sync(0xFFFFFFFF, sl, 2);
            sh += __shfl_xor_sync(0xFFFFFFFF, sh, 1);
            sh += __shfl_xor_sync(0xFFFFFFFF, sh, 2);
            rlo[mt] = sl; rhi[mt] = sh;
        }

        // col sums
        float cp0[8], cp1[8];
#pragma unroll
        for (int nt = 0; nt < 8; nt++) {
            float c0 = (ev[0][nt][0] + ev[0][nt][2]) + (ev[1][nt][0] + ev[1][nt][2]);
            float c1 = (ev[0][nt][1] + ev[0][nt][3]) + (ev[1][nt][1] + ev[1][nt][3]);
            c0 += __shfl_xor_sync(0xFFFFFFFF, c0, 4);
            c0 += __shfl_xor_sync(0xFFFFFFFF, c0, 8);
            c0 += __shfl_xor_sync(0xFFFFFFFF, c0, 16);
            c1 += __shfl_xor_sync(0xFFFFFFFF, c1, 4);
            c1 += __shfl_xor_sync(0xFFFFFFFF, c1, 8);
            c1 += __shfl_xor_sync(0xFFFFFFFF, c1, 16);
            cp0[nt] = c0; cp1[nt] = c1;
        }

        if ((lane & 3) == 0) {
#pragma unroll
            for (int mt = 0; mt < 2; mt++) {
                int r = wy * 32 + mt * 16 + (lane >> 2);
                red_row[r * 2 + wx] = rlo[mt];
                red_row[(r + 8) * 2 + wx] = rhi[mt];
            }
        }
        if (lane < 4) {
#pragma unroll
            for (int nt = 0; nt < 8; nt++) {
                int c = wx * 64 + nt * 8 + lane * 2;
                red_col[c * 4 + wy] = cp0[nt];
                red_col[(c + 1) * 4 + wy] = cp1[nt];
            }
        }
        __syncthreads();
        if (tid < 128) {
            float rz = red_row[tid * 2] + red_row[tid * 2 + 1];
            g_Zp[(size_t)(I * 128 + tid) * NT_ROW + J] = rz;
            if (!dt) {
                float cz = (red_col[tid * 4] + red_col[tid * 4 + 1]) +
                           (red_col[tid * 4 + 2] + red_col[tid * 4 + 3]);
                g_Zp[(size_t)(J * 128 + tid) * NT_ROW + I] = cz;
            }
        }
        CP_WAIT0();
        __syncthreads();

        I = I1; J = J1;
    }
}

// ---------------- 5) per-row contrastive loss ---------------------------------------
__global__ void k_con(const int* __restrict__ tgt) {
    int w = threadIdx.x >> 5, lane = threadIdx.x & 31;
    int row = blockIdx.x * 8 + w;
    int t = tgt[row];
    float zs = g_Zp[(size_t)row * NT_ROW + lane] + g_Zp[(size_t)row * NT_ROW + lane + 32];
    const float4* e = (const float4*)&g_embn[row * DIM];
    const float4* sc = (const float4*)&g_clsum[t * DIM];
    float dot = 0.f;
#pragma unroll
    for (int k = lane; k < DIM / 4; k += 32) {
        float4 a = e[k], b = sc[k];
        dot += a.x * b.x + a.y * b.y + a.z * b.z + a.w * b.w;
    }
#pragma unroll
    for (int off = 16; off > 0; off >>= 1) {
        dot += __shfl_xor_sync(0xFFFFFFFF, dot, off);
        zs += __shfl_xor_sync(0xFFFFFFFF, zs, off);
    }
    if (lane == 0) {
        float logZ = logf(zs + 1e-8f);
        float npos = g_clcnt[t] - 1.0f;
        float msum = (dot - 1.0f) * INV_T;
        g_con[row] = (npos * logZ - msum) / fmaxf(npos, 1.0f);
    }
}

// ---------------- 6) final reduction -------------------------------------------------
__global__ void k_final(float* __restrict__ out, int out_size) {
    __shared__ float s[256];
    int t = threadIdx.x;

    float cs = 0.f;
    for (int i = t; i < N; i += 256) cs += g_con[i];
    s[t] = cs;
    __syncthreads();
    for (int off = 128; off > 0; off >>= 1) {
        if (t < off) s[t] += s[t + off];
        __syncthreads();
    }
    __shared__ float con_sum;
    if (t == 0) con_sum = s[0];
    __syncthreads();

    s[t] = (t < 32) ? g_ce_part[t] : 0.f;
    __syncthreads();
    for (int off = 128; off > 0; off >>= 1) {
        if (t < off) s[t] += s[t + off];
        __syncthreads();
    }
    if (t == 0) {
        float ce_mean = s[0] * (1.0f / N);
        float con_mean = con_sum * (1.0f / N);
        out[0] = ce_mean + ALPHA * con_mean;
        if (out_size > 1) out[1] = ce_mean;
        if (out_size > 2) out[2] = con_mean;
    }
}

// ---------------- launcher ----------------------------------------------------------
extern "C" void kernel_launch(void* const* d_in, const int* in_sizes, int n_in,
                              void* d_out, int out_size) {
    const float* logits = (const float*)d_in[0];
    const float* emb = (const float*)d_in[1];
    const int* tgt = (const int*)d_in[2];
    float* out = (float*)d_out;

    cudaFuncSetAttribute(k_sim_sym, cudaFuncAttributeMaxDynamicSharedMemorySize, SMEM_TOTAL);

    k_norm<<<N, DIM>>>(emb);
    k_clspart<<<32, 256>>>(tgt);
    k_clsfinal<<<CLS, DIM>>>();
    k_ce<<<N / 256, 256>>>(logits, tgt);
    k_sim_sym<<<130, 256, SMEM_TOTAL>>>();
    k_con<<<N / 8, 256>>>(tgt);
    k_final<<<1, 256>>>(out, out_size);
}

// round 7
// speedup vs baseline: 1.0053x; 1.0053x over previous
#include <cuda_runtime.h>
#include <math.h>
#include <stdint.h>

#define N 8192
#define CLS 8
#define DIM 256
#define INV_T 14.285714285714286f
#define EXP_SCALE 20.60992915555662f   /* (1/0.07) * log2(e) */
#define ALPHA 0.3f
#define LSM 0.1f
#define NT_ROW 64

// ---------------- scratch ------------------------------------------------------------
__device__ float g_embn[N * DIM];
__device__ uint16_t g_embq[N * DIM / 2];     // e4m3 pairs (256 B/row)
__device__ float g_clsum_part[32 * CLS * DIM];
__device__ float g_clcnt_part[32 * CLS];
__device__ float g_clsum[CLS * DIM];
__device__ float g_clcnt[CLS];
__device__ float g_Zp[N * NT_ROW];
__device__ float g_con[N];
__device__ float g_ce_part[32];

// ---------------- helpers ------------------------------------------------------------
__device__ __forceinline__ uint32_t smem_u32(const void* p) {
    uint32_t a;
    asm("{ .reg .u64 t; cvta.to.shared.u64 t, %1; cvt.u32.u64 %0, t; }" : "=r"(a) : "l"(p));
    return a;
}
__device__ __forceinline__ float ex2f(float x) {
    float y; asm("ex2.approx.f32 %0, %1;" : "=f"(y) : "f"(x)); return y;
}
__device__ __forceinline__ void cp16(uint32_t dst, const void* src) {
    asm volatile("cp.async.cg.shared.global [%0], [%1], 16;" :: "r"(dst), "l"(src));
}
#define CP_COMMIT() asm volatile("cp.async.commit_group;" ::: "memory")
#define CP_WAIT0()  asm volatile("cp.async.wait_group 0;" ::: "memory")

__device__ __forceinline__ void ldsm4(uint32_t& r0, uint32_t& r1, uint32_t& r2, uint32_t& r3,
                                      uint32_t addr) {
    asm volatile("ldmatrix.sync.aligned.m8n8.x4.shared.b16 {%0,%1,%2,%3}, [%4];"
                 : "=r"(r0), "=r"(r1), "=r"(r2), "=r"(r3) : "r"(addr));
}
__device__ __forceinline__ void mma_fp8(float* c, uint32_t a0, uint32_t a1, uint32_t a2,
                                        uint32_t a3, uint32_t b0, uint32_t b1) {
    asm volatile("mma.sync.aligned.m16n8k32.row.col.f32.e4m3.e4m3.f32 "
                 "{%0,%1,%2,%3}, {%4,%5,%6,%7}, {%8,%9}, {%0,%1,%2,%3};"
                 : "+f"(c[0]), "+f"(c[1]), "+f"(c[2]), "+f"(c[3])
                 : "r"(a0), "r"(a1), "r"(a2), "r"(a3), "r"(b0), "r"(b1));
}
__device__ __forceinline__ uint16_t f2e4m3x2(float hi, float lo) {
    uint16_t r;
    asm("cvt.rn.satfinite.e4m3x2.f32 %0, %1, %2;" : "=h"(r) : "f"(hi), "f"(lo));
    return r;
}

// ---------------- 1) normalize + fp8 convert ----------------------------------------
__global__ void k_norm(const float* __restrict__ emb) {
    int row = blockIdx.x;
    int d = threadIdx.x;
    float v = emb[row * DIM + d];
    __shared__ float s[DIM];
    __shared__ float sv[DIM];
    s[d] = v * v;
    __syncthreads();
    for (int off = DIM / 2; off > 0; off >>= 1) {
        if (d < off) s[d] += s[d + off];
        __syncthreads();
    }
    float norm = fmaxf(sqrtf(s[0]), 1e-12f);
    float nv = v / norm;
    g_embn[row * DIM + d] = nv;
    sv[d] = nv;
    __syncthreads();
    if (d < DIM / 2) {
        g_embq[row * (DIM / 2) + d] = f2e4m3x2(sv[2 * d + 1], sv[2 * d]);
    }
}

// ---------------- 2) class sums ------------------------------------------------------
__global__ void k_clspart(const int* __restrict__ tgt) {
    int b = blockIdx.x, d = threadIdx.x;
    int i0 = b * 256;
    __shared__ int st[256];
    st[d] = tgt[i0 + d];
    __syncthreads();
    float a[CLS];
#pragma unroll
    for (int c = 0; c < CLS; c++) a[c] = 0.f;
    for (int k = 0; k < 256; k++) {
        float v = g_embn[(i0 + k) * DIM + d];
        int t = st[k];
#pragma unroll
        for (int c = 0; c < CLS; c++) a[c] += (t == c) ? v : 0.f;
    }
#pragma unroll
    for (int c = 0; c < CLS; c++) g_clsum_part[(b * CLS + c) * DIM + d] = a[c];
    if (d == 0) {
        int cnt[CLS];
#pragma unroll
        for (int c = 0; c < CLS; c++) cnt[c] = 0;
        for (int k = 0; k < 256; k++) {
#pragma unroll
            for (int c = 0; c < CLS; c++) cnt[c] += (st[k] == c);
        }
#pragma unroll
        for (int c = 0; c < CLS; c++) g_clcnt_part[b * CLS + c] = (float)cnt[c];
    }
}

__global__ void k_clsfinal() {
    int c = blockIdx.x, d = threadIdx.x;
    float s = 0.f;
    for (int b = 0; b < 32; b++) s += g_clsum_part[(b * CLS + c) * DIM + d];
    g_clsum[c * DIM + d] = s;
    if (d == 0) {
        float cn = 0.f;
        for (int b = 0; b < 32; b++) cn += g_clcnt_part[b * CLS + c];
        g_clcnt[c] = cn;
    }
}

// ---------------- 3) focal cross-entropy --------------------------------------------
__global__ void k_ce(const float* __restrict__ logits, const int* __restrict__ tgt) {
    int i = blockIdx.x * 256 + threadIdx.x;
    const float4* p = (const float4*)(logits + i * CLS);
    float4 u = p[0], w = p[1];
    float x[CLS] = {u.x, u.y, u.z, u.w, w.x, w.y, w.z, w.w};
    float m = x[0];
#pragma unroll
    for (int j = 1; j < CLS; j++) m = fmaxf(m, x[j]);
    float se = 0.f;
#pragma unroll
    for (int j = 0; j < CLS; j++) se += expf(x[j] - m);
    float lse = m + logf(se);
    int t = tgt[i];
    float nll = lse - x[t];
    float sx = 0.f;
#pragma unroll
    for (int j = 0; j < CLS; j++) sx += x[j];
    float smooth = lse - sx * (1.0f / CLS);
    float ce = (1.0f - LSM) * nll + LSM * smooth;
    float pt = expf(-ce);
    float omp = 1.0f - pt;
    float focal = omp * omp * ce;

    __shared__ float s[256];
    s[threadIdx.x] = focal;
    __syncthreads();
    for (int off = 128; off > 0; off >>= 1) {
        if (threadIdx.x < off) s[threadIdx.x] += s[threadIdx.x + off];
        __syncthreads();
    }
    if (threadIdx.x == 0) g_ce_part[blockIdx.x] = s[0];
}

// ---------------- 4) HOT: symmetric Z, fp8 mma, 512 threads (16 warps, 32x32 tiles) --
#define SAB 272
#define A_BYTES (128 * SAB)              /* 34816 */
#define AS_OFF 0
#define BS_OFF(b) (A_BYTES + (b) * A_BYTES)
#define RED_OFF (3 * A_BYTES)            /* 104448 */
#define SMEM_TOTAL (RED_OFF + 128 * 4 * 4 + 128 * 4 * 4)

__device__ __forceinline__ void load_tile_async(uint32_t sbase, int grow0, int tid) {
    const char* src = (const char*)g_embq + (size_t)grow0 * 256;
#pragma unroll
    for (int i = 0; i < 4; i++) {
        int idx = tid + i * 512;
        int row = idx >> 4, cb = idx & 15;
        cp16(sbase + row * SAB + cb * 16, src + (size_t)row * 256 + cb * 16);
    }
}

__global__ void __launch_bounds__(512, 1) k_sim_sym() {
    extern __shared__ char smem[];
    uint32_t sb = smem_u32(smem);
    float* red_row = (float*)(smem + RED_OFF);          // [128][4]
    float* red_col = (float*)(smem + RED_OFF + 2048);   // [128][4]
    int tid = threadIdx.x;
    int lane = tid & 31;
    int wid = tid >> 5;
    int wx = wid & 3;          // N dir (4 x 32 cols)
    int wy = wid >> 2;         // M dir (4 x 32 rows)

    int rem = blockIdx.x * 16;
    int I = 0;
    while (rem >= NT_ROW - I) { rem -= NT_ROW - I; I++; }
    int J = I + rem;

    uint32_t a_addr = sb + AS_OFF + (wy * 32 + (lane & 15)) * SAB + ((lane >> 4) << 4);
    uint32_t b_addr = sb + ((lane & 7) + ((lane >> 4) << 3)) * SAB + (((lane >> 3) & 1) << 4);
    uint32_t b_base = b_addr + (wx * 32) * SAB;

    const float EXP_DIAG = expf(INV_T);
    int lrl0 = wy * 32 + (lane >> 2);          // local row (mt=0, lo half)
    int lcb0 = wx * 32 + (lane & 3) * 2;       // local col base (nt=0)

    int curI = -1;

    for (int k = 0; k < 16; k++) {
        int buf = k & 1;
        if (I != curI) {
            load_tile_async(sb + AS_OFF, I * 128, tid);
            if (k == 0) load_tile_async(sb + BS_OFF(0), J * 128, tid);
            CP_COMMIT();
            CP_WAIT0();
            __syncthreads();
            curI = I;
        }
        int I1 = I, J1 = J + 1;
        if (J1 == NT_ROW) { I1 = I + 1; J1 = I1; }
        if (k + 1 < 16) {
            load_tile_async(sb + BS_OFF(buf ^ 1), J1 * 128, tid);
            CP_COMMIT();
        }

        // ---- MMA: warp tile 32x32, 8 K-steps of 32 ----
        float acc[2][4][4];
#pragma unroll
        for (int mt = 0; mt < 2; mt++)
#pragma unroll
            for (int nt = 0; nt < 4; nt++)
#pragma unroll
                for (int q = 0; q < 4; q++) acc[mt][nt][q] = 0.f;

        uint32_t bbuf = b_base + BS_OFF(buf);
#pragma unroll
        for (int ks = 0; ks < 8; ks++) {
            uint32_t koff = ks * 32;
            uint32_t a0[4], a1[4];
            ldsm4(a0[0], a0[1], a0[2], a0[3], a_addr + koff);
            ldsm4(a1[0], a1[1], a1[2], a1[3], a_addr + 16 * SAB + koff);
            uint32_t bfr[2][4];
#pragma unroll
            for (int p = 0; p < 2; p++)
                ldsm4(bfr[p][0], bfr[p][1], bfr[p][2], bfr[p][3],
                      bbuf + (p * 16) * SAB + koff);
#pragma unroll
            for (int nt = 0; nt < 4; nt++) {
                uint32_t bb0 = bfr[nt >> 1][(nt & 1) * 2];
                uint32_t bb1 = bfr[nt >> 1][(nt & 1) * 2 + 1];
                mma_fp8(acc[0][nt], a0[0], a0[1], a0[2], a0[3], bb0, bb1);
                mma_fp8(acc[1][nt], a1[0], a1[1], a1[2], a1[3], bb0, bb1);
            }
        }

        // ---- epilogue ----
        bool dt = (I == J);
        float ev[2][4][4];
#pragma unroll
        for (int mt = 0; mt < 2; mt++) {
            int lr = lrl0 + mt * 16;
#pragma unroll
            for (int nt = 0; nt < 4; nt++) {
                int lc = lcb0 + nt * 8;
                ev[mt][nt][0] = (dt && lc == lr)         ? EXP_DIAG : ex2f(acc[mt][nt][0] * EXP_SCALE);
                ev[mt][nt][1] = (dt && lc + 1 == lr)     ? EXP_DIAG : ex2f(acc[mt][nt][1] * EXP_SCALE);
                ev[mt][nt][2] = (dt && lc == lr + 8)     ? EXP_DIAG : ex2f(acc[mt][nt][2] * EXP_SCALE);
                ev[mt][nt][3] = (dt && lc + 1 == lr + 8) ? EXP_DIAG : ex2f(acc[mt][nt][3] * EXP_SCALE);
            }
        }

        // row sums: over nt in-thread, then quad lanes
        float rlo[2], rhi[2];
#pragma unroll
        for (int mt = 0; mt < 2; mt++) {
            float sl = 0.f, sh = 0.f;
#pragma unroll
            for (int nt = 0; nt < 4; nt++) {
                sl += ev[mt][nt][0] + ev[mt][nt][1];
                sh += ev[mt][nt][2] + ev[mt][nt][3];
            }
            sl += __shfl_xor_sync(0xFFFFFFFF, sl, 1);
            sl += __shfl_xor_sync(0xFFFFFFFF, sl, 2);
            sh += __shfl_xor_sync(0xFFFFFFFF, sh, 1);
            sh += __shfl_xor_sync(0xFFFFFFFF, sh, 2);
            rlo[mt] = sl; rhi[mt] = sh;
        }

        // col sums: over mt + halves in-thread, then lane>>2 groups
        float cp0[4], cp1[4];
#pragma unroll
        for (int nt = 0; nt < 4; nt++) {
            float c0 = (ev[0][nt][0] + ev[0][nt][2]) + (ev[1][nt][0] + ev[1][nt][2]);
            float c1 = (ev[0][nt][1] + ev[0][nt][3]) + (ev[1][nt][1] + ev[1][nt][3]);
            c0 += __shfl_xor_sync(0xFFFFFFFF, c0, 4);
            c0 += __shfl_xor_sync(0xFFFFFFFF, c0, 8);
            c0 += __shfl_xor_sync(0xFFFFFFFF, c0, 16);
            c1 += __shfl_xor_sync(0xFFFFFFFF, c1, 4);
            c1 += __shfl_xor_sync(0xFFFFFFFF, c1, 8);
            c1 += __shfl_xor_sync(0xFFFFFFFF, c1, 16);
            cp0[nt] = c0; cp1[nt] = c1;
        }

        if ((lane & 3) == 0) {
#pragma unroll
            for (int mt = 0; mt < 2; mt++) {
                int r = wy * 32 + mt * 16 + (lane >> 2);
                red_row[r * 4 + wx] = rlo[mt];
                red_row[(r + 8) * 4 + wx] = rhi[mt];
            }
        }
        if (lane < 4) {
#pragma unroll
            for (int nt = 0; nt < 4; nt++) {
                int c = wx * 32 + nt * 8 + lane * 2;
                red_col[c * 4 + wy] = cp0[nt];
                red_col[(c + 1) * 4 + wy] = cp1[nt];
            }
        }
        __syncthreads();
        if (tid < 128) {
            float rz = (red_row[tid * 4] + red_row[tid * 4 + 1]) +
                       (red_row[tid * 4 + 2] + red_row[tid * 4 + 3]);
            g_Zp[(size_t)(I * 128 + tid) * NT_ROW + J] = rz;
            if (!dt) {
                float cz = (red_col[tid * 4] + red_col[tid * 4 + 1]) +
                           (red_col[tid * 4 + 2] + red_col[tid * 4 + 3]);
                g_Zp[(size_t)(J * 128 + tid) * NT_ROW + I] = cz;
            }
        }
        CP_WAIT0();
        __syncthreads();

        I = I1; J = J1;
    }
}

// ---------------- 5) per-row contrastive loss ---------------------------------------
__global__ void k_con(const int* __restrict__ tgt) {
    int w = threadIdx.x >> 5, lane = threadIdx.x & 31;
    int row = blockIdx.x * 8 + w;
    int t = tgt[row];
    float zs = g_Zp[(size_t)row * NT_ROW + lane] + g_Zp[(size_t)row * NT_ROW + lane + 32];
    const float4* e = (const float4*)&g_embn[row * DIM];
    const float4* sc = (const float4*)&g_clsum[t * DIM];
    float dot = 0.f;
#pragma unroll
    for (int k = lane; k < DIM / 4; k += 32) {
        float4 a = e[k], b = sc[k];
        dot += a.x * b.x + a.y * b.y + a.z * b.z + a.w * b.w;
    }
#pragma unroll
    for (int off = 16; off > 0; off >>= 1) {
        dot += __shfl_xor_sync(0xFFFFFFFF, dot, off);
        zs += __shfl_xor_sync(0xFFFFFFFF, zs, off);
    }
    if (lane == 0) {
        float logZ = logf(zs + 1e-8f);
        float npos = g_clcnt[t] - 1.0f;
        float msum = (dot - 1.0f) * INV_T;
        g_con[row] = (npos * logZ - msum) / fmaxf(npos, 1.0f);
    }
}

// ---------------- 6) final reduction -------------------------------------------------
__global__ void k_final(float* __restrict__ out, int out_size) {
    __shared__ float s[256];
    int t = threadIdx.x;

    float cs = 0.f;
    for (int i = t; i < N; i += 256) cs += g_con[i];
    s[t] = cs;
    __syncthreads();
    for (int off = 128; off > 0; off >>= 1) {
        if (t < off) s[t] += s[t + off];
        __syncthreads();
    }
    __shared__ float con_sum;
    if (t == 0) con_sum = s[0];
    __syncthreads();

    s[t] = (t < 32) ? g_ce_part[t] : 0.f;
    __syncthreads();
    for (int off = 128; off > 0; off >>= 1) {
        if (t < off) s[t] += s[t + off];
        __syncthreads();
    }
    if (t == 0) {
        float ce_mean = s[0] * (1.0f / N);
        float con_mean = con_sum * (1.0f / N);
        out[0] = ce_mean + ALPHA * con_mean;
        if (out_size > 1) out[1] = ce_mean;
        if (out_size > 2) out[2] = con_mean;
    }
}

// ---------------- launcher ----------------------------------------------------------
extern "C" void kernel_launch(void* const* d_in, const int* in_sizes, int n_in,
                              void* d_out, int out_size) {
    const float* logits = (const float*)d_in[0];
    const float* emb = (const float*)d_in[1];
    const int* tgt = (const int*)d_in[2];
    float* out = (float*)d_out;

    cudaFuncSetAttribute(k_sim_sym, cudaFuncAttributeMaxDynamicSharedMemorySize, SMEM_TOTAL);

    k_norm<<<N, DIM>>>(emb);
    k_clspart<<<32, 256>>>(tgt);
    k_clsfinal<<<CLS, DIM>>>();
    k_ce<<<N / 256, 256>>>(logits, tgt);
    k_sim_sym<<<130, 512, SMEM_TOTAL>>>();
    k_con<<<N / 8, 256>>>(tgt);
    k_final<<<1, 256>>>(out, out_size);
}

// round 8
// speedup vs baseline: 1.3951x; 1.3877x over previous
#include <cuda_runtime.h>
#include <math.h>
#include <stdint.h>

#define N 8192
#define CLS 8
#define DIM 256
#define INV_T 14.285714285714286f
#define EXP_SCALE 20.60992915555662f   /* (1/0.07) * log2(e) */
#define ALPHA 0.3f
#define LSM 0.1f
#define NT_ROW 64
#define NCHUNK 64

// ---------------- scratch ------------------------------------------------------------
__device__ float g_embn[N * DIM];
__device__ uint16_t g_embq[N * DIM / 2];     // e4m3 pairs (256 B/row)
__device__ float g_clsum_part[NCHUNK * CLS * DIM];
__device__ float g_clcnt_part[NCHUNK * CLS];
__device__ float g_clsum[CLS * DIM];
__device__ float g_clcnt[CLS];
__device__ float g_Zp[N * NT_ROW];
__device__ float g_con[N];
__device__ float g_ce_part[32];

// ---------------- helpers ------------------------------------------------------------
__device__ __forceinline__ uint32_t smem_u32(const void* p) {
    uint32_t a;
    asm("{ .reg .u64 t; cvta.to.shared.u64 t, %1; cvt.u32.u64 %0, t; }" : "=r"(a) : "l"(p));
    return a;
}
__device__ __forceinline__ float ex2f(float x) {
    float y; asm("ex2.approx.f32 %0, %1;" : "=f"(y) : "f"(x)); return y;
}
__device__ __forceinline__ void cp16(uint32_t dst, const void* src) {
    asm volatile("cp.async.cg.shared.global [%0], [%1], 16;" :: "r"(dst), "l"(src));
}
#define CP_COMMIT() asm volatile("cp.async.commit_group;" ::: "memory")
#define CP_WAIT0()  asm volatile("cp.async.wait_group 0;" ::: "memory")

__device__ __forceinline__ void ldsm4(uint32_t& r0, uint32_t& r1, uint32_t& r2, uint32_t& r3,
                                      uint32_t addr) {
    asm volatile("ldmatrix.sync.aligned.m8n8.x4.shared.b16 {%0,%1,%2,%3}, [%4];"
                 : "=r"(r0), "=r"(r1), "=r"(r2), "=r"(r3) : "r"(addr));
}
__device__ __forceinline__ void mma_fp8(float* c, uint32_t a0, uint32_t a1, uint32_t a2,
                                        uint32_t a3, uint32_t b0, uint32_t b1) {
    asm volatile("mma.sync.aligned.m16n8k32.row.col.f32.e4m3.e4m3.f32 "
                 "{%0,%1,%2,%3}, {%4,%5,%6,%7}, {%8,%9}, {%0,%1,%2,%3};"
                 : "+f"(c[0]), "+f"(c[1]), "+f"(c[2]), "+f"(c[3])
                 : "r"(a0), "r"(a1), "r"(a2), "r"(a3), "r"(b0), "r"(b1));
}
__device__ __forceinline__ uint16_t f2e4m3x2(float hi, float lo) {
    uint16_t r;
    asm("cvt.rn.satfinite.e4m3x2.f32 %0, %1, %2;" : "=h"(r) : "f"(hi), "f"(lo));
    return r;
}

// ---------------- 1) normalize + fp8 convert (warp per row) --------------------------
__global__ void k_norm(const float* __restrict__ emb) {
    int w = threadIdx.x >> 5, lane = threadIdx.x & 31;
    int row = blockIdx.x * 8 + w;
    const float4* src = (const float4*)(emb + (size_t)row * DIM);
    float4 v0 = src[lane * 2], v1 = src[lane * 2 + 1];
    float ss = v0.x * v0.x + v0.y * v0.y + v0.z * v0.z + v0.w * v0.w +
               v1.x * v1.x + v1.y * v1.y + v1.z * v1.z + v1.w * v1.w;
#pragma unroll
    for (int off = 16; off > 0; off >>= 1) ss += __shfl_xor_sync(0xFFFFFFFF, ss, off);
    float norm = fmaxf(sqrtf(ss), 1e-12f);
    float inv = 1.0f / norm;
    v0.x *= inv; v0.y *= inv; v0.z *= inv; v0.w *= inv;
    v1.x *= inv; v1.y *= inv; v1.z *= inv; v1.w *= inv;
    float4* dst = (float4*)(g_embn + (size_t)row * DIM);
    dst[lane * 2] = v0;
    dst[lane * 2 + 1] = v1;
    uint32_t u0 = (uint32_t)f2e4m3x2(v0.y, v0.x) | ((uint32_t)f2e4m3x2(v0.w, v0.z) << 16);
    uint32_t u1 = (uint32_t)f2e4m3x2(v1.y, v1.x) | ((uint32_t)f2e4m3x2(v1.w, v1.z) << 16);
    *(uint2*)(g_embq + (size_t)row * 128 + lane * 4) = make_uint2(u0, u1);
}

// ---------------- 2) class sums (64 chunks of 128 rows) ------------------------------
__global__ void k_clspart(const int* __restrict__ tgt) {
    int b = blockIdx.x, d = threadIdx.x;
    int i0 = b * 128;
    __shared__ int st[128];
    if (d < 128) st[d] = tgt[i0 + d];
    __syncthreads();
    float a[CLS];
#pragma unroll
    for (int c = 0; c < CLS; c++) a[c] = 0.f;
    for (int k = 0; k < 128; k++) {
        float v = g_embn[(size_t)(i0 + k) * DIM + d];
        int t = st[k];
#pragma unroll
        for (int c = 0; c < CLS; c++) a[c] += (t == c) ? v : 0.f;
    }
#pragma unroll
    for (int c = 0; c < CLS; c++) g_clsum_part[(b * CLS + c) * DIM + d] = a[c];
    if (d == 0) {
        int cnt[CLS];
#pragma unroll
        for (int c = 0; c < CLS; c++) cnt[c] = 0;
        for (int k = 0; k < 128; k++) {
#pragma unroll
            for (int c = 0; c < CLS; c++) cnt[c] += (st[k] == c);
        }
#pragma unroll
        for (int c = 0; c < CLS; c++) g_clcnt_part[b * CLS + c] = (float)cnt[c];
    }
}

__global__ void k_clsfinal() {
    int c = blockIdx.x, d = threadIdx.x;
    float s = 0.f;
    for (int b = 0; b < NCHUNK; b++) s += g_clsum_part[(b * CLS + c) * DIM + d];
    g_clsum[c * DIM + d] = s;
    if (d == 0) {
        float cn = 0.f;
        for (int b = 0; b < NCHUNK; b++) cn += g_clcnt_part[b * CLS + c];
        g_clcnt[c] = cn;
    }
}

// ---------------- 3) focal cross-entropy --------------------------------------------
__global__ void k_ce(const float* __restrict__ logits, const int* __restrict__ tgt) {
    int i = blockIdx.x * 256 + threadIdx.x;
    const float4* p = (const float4*)(logits + (size_t)i * CLS);
    float4 u = p[0], w = p[1];
    float x[CLS] = {u.x, u.y, u.z, u.w, w.x, w.y, w.z, w.w};
    float m = x[0];
#pragma unroll
    for (int j = 1; j < CLS; j++) m = fmaxf(m, x[j]);
    float se = 0.f;
#pragma unroll
    for (int j = 0; j < CLS; j++) se += expf(x[j] - m);
    float lse = m + logf(se);
    int t = tgt[i];
    float nll = lse - x[t];
    float sx = 0.f;
#pragma unroll
    for (int j = 0; j < CLS; j++) sx += x[j];
    float smooth = lse - sx * (1.0f / CLS);
    float ce = (1.0f - LSM) * nll + LSM * smooth;
    float pt = expf(-ce);
    float omp = 1.0f - pt;
    float focal = omp * omp * ce;

    __shared__ float s[256];
    s[threadIdx.x] = focal;
    __syncthreads();
    for (int off = 128; off > 0; off >>= 1) {
        if (threadIdx.x < off) s[threadIdx.x] += s[threadIdx.x + off];
        __syncthreads();
    }
    if (threadIdx.x == 0) g_ce_part[blockIdx.x] = s[0];
}

// ---------------- 4) HOT: symmetric Z, fp8 mma, pipelined epilogue -------------------
// 148 CTAs x 14/15 tiles (2080 total). 512 threads, 16 warps (4x4), warp tile 32x32.
// Tile t's epilogue (exp + partial sums) is interleaved into tile t+1's MMA K-loop.
// One __syncthreads per tile; reduction staging double-buffered by tile parity.
#define SAB 272
#define A_BYTES (128 * SAB)              /* 34816 */
#define AS_OFF 0
#define BS_OFF(b) (A_BYTES + (b) * A_BYTES)
#define RED_OFF (3 * A_BYTES)            /* 104448 */
#define RED_PAR 4096                     /* bytes per parity: row 2048 + col 2048 */
#define SMEM_TOTAL (RED_OFF + 2 * RED_PAR)

__device__ __forceinline__ void load_tile_async(uint32_t sbase, int grow0, int tid) {
    const char* src = (const char*)g_embq + (size_t)grow0 * 256;
#pragma unroll
    for (int i = 0; i < 4; i++) {
        int idx = tid + i * 512;
        int row = idx >> 4, cb = idx & 15;
        cp16(sbase + row * SAB + cb * 16, src + (size_t)row * 256 + cb * 16);
    }
}

__global__ void __launch_bounds__(512, 1) k_sim_sym() {
    extern __shared__ char smem[];
    uint32_t sb = smem_u32(smem);
    int tid = threadIdx.x;
    int lane = tid & 31;
    int wid = tid >> 5;
    int wx = wid & 3;
    int wy = wid >> 2;
    int bid = blockIdx.x;

    // balanced schedule: first 8 CTAs do 15 tiles, rest 14
    int base = bid * 14 + (bid < 8 ? bid : 8);
    int cnt = 14 + (bid < 8 ? 1 : 0);

    int idx = base, I = 0;
    while (idx >= NT_ROW - I) { idx -= NT_ROW - I; I++; }
    int J = I + idx;

    uint32_t a_addr = sb + AS_OFF + (wy * 32 + (lane & 15)) * SAB + ((lane >> 4) << 4);
    uint32_t b_addr = sb + ((lane & 7) + ((lane >> 4) << 3)) * SAB + (((lane >> 3) & 1) << 4);
    uint32_t b_base = b_addr + (wx * 32) * SAB;

    const float EXP_DIAG = expf(INV_T);
    int lrl0 = wy * 32 + (lane >> 2);
    int lcb0 = wx * 32 + (lane & 3) * 2;

    float prev[2][4][4];
    int Ip = 0, Jp = 0;
    bool dtp = false;
    bool ready = false;

    for (int t = 0; t < cnt; t++) {
        if (!ready) {   // first tile or row-change: load A + B serially
            load_tile_async(sb + AS_OFF, I * 128, tid);
            load_tile_async(sb + BS_OFF(t & 1), J * 128, tid);
            CP_COMMIT();
            CP_WAIT0();
            __syncthreads();
        }
        // next tile coords + prefetch (same row only)
        int I1 = I, J1 = J + 1;
        if (J1 == NT_ROW) { I1 = I + 1; J1 = I1; }
        bool pf = (t + 1 < cnt) && (I1 == I);
        if (pf) {
            load_tile_async(sb + BS_OFF((t + 1) & 1), J1 * 128, tid);
            CP_COMMIT();
        }

        // ---- MMA tile t interleaved with epilogue of tile t-1 ----
        float acc[2][4][4];
#pragma unroll
        for (int mt = 0; mt < 2; mt++)
#pragma unroll
            for (int nt = 0; nt < 4; nt++)
#pragma unroll
                for (int q = 0; q < 4; q++) acc[mt][nt][q] = 0.f;

        float rlo[2] = {0.f, 0.f}, rhi[2] = {0.f, 0.f};
        float cp0[4] = {0.f, 0.f, 0.f, 0.f}, cp1[4] = {0.f, 0.f, 0.f, 0.f};

        uint32_t bbuf = b_base + BS_OFF(t & 1);
#pragma unroll
        for (int ks = 0; ks < 8; ks++) {
            uint32_t koff = ks * 32;
            uint32_t a0[4], a1[4];
            ldsm4(a0[0], a0[1], a0[2], a0[3], a_addr + koff);
            ldsm4(a1[0], a1[1], a1[2], a1[3], a_addr + 16 * SAB + koff);
            uint32_t bfr[2][4];
#pragma unroll
            for (int p = 0; p < 2; p++)
                ldsm4(bfr[p][0], bfr[p][1], bfr[p][2], bfr[p][3],
                      bbuf + (p * 16) * SAB + koff);
#pragma unroll
            for (int nt = 0; nt < 4; nt++) {
                uint32_t bb0 = bfr[nt >> 1][(nt & 1) * 2];
                uint32_t bb1 = bfr[nt >> 1][(nt & 1) * 2 + 1];
                mma_fp8(acc[0][nt], a0[0], a0[1], a0[2], a0[3], bb0, bb1);
                mma_fp8(acc[1][nt], a1[0], a1[1], a1[2], a1[3], bb0, bb1);
            }
            // epilogue chunk of previous tile: values prev[mt][nt][0..3]
            if (t > 0) {
                int mt = ks & 1, nt = ks >> 1;
                int lr = lrl0 + mt * 16;
                int lc = lcb0 + nt * 8;
                float v0 = (dtp && lc == lr)         ? EXP_DIAG : ex2f(prev[mt][nt][0] * EXP_SCALE);
                float v1 = (dtp && lc + 1 == lr)     ? EXP_DIAG : ex2f(prev[mt][nt][1] * EXP_SCALE);
                float v2 = (dtp && lc == lr + 8)     ? EXP_DIAG : ex2f(prev[mt][nt][2] * EXP_SCALE);
                float v3 = (dtp && lc + 1 == lr + 8) ? EXP_DIAG : ex2f(prev[mt][nt][3] * EXP_SCALE);
                rlo[mt] += v0 + v1;
                rhi[mt] += v2 + v3;
                cp0[nt] += v0 + v2;
                cp1[nt] += v1 + v3;
            }
        }

        // ---- reduce + store previous tile's sums (parity (t-1)&1) ----
        if (t > 0) {
            float* red_row = (float*)(smem + RED_OFF + ((t - 1) & 1) * RED_PAR);
            float* red_col = red_row + 512;
#pragma unroll
            for (int mt = 0; mt < 2; mt++) {
                rlo[mt] += __shfl_xor_sync(0xFFFFFFFF, rlo[mt], 1);
                rlo[mt] += __shfl_xor_sync(0xFFFFFFFF, rlo[mt], 2);
                rhi[mt] += __shfl_xor_sync(0xFFFFFFFF, rhi[mt], 1);
                rhi[mt] += __shfl_xor_sync(0xFFFFFFFF, rhi[mt], 2);
            }
#pragma unroll
            for (int nt = 0; nt < 4; nt++) {
                cp0[nt] += __shfl_xor_sync(0xFFFFFFFF, cp0[nt], 4);
                cp0[nt] += __shfl_xor_sync(0xFFFFFFFF, cp0[nt], 8);
                cp0[nt] += __shfl_xor_sync(0xFFFFFFFF, cp0[nt], 16);
                cp1[nt] += __shfl_xor_sync(0xFFFFFFFF, cp1[nt], 4);
                cp1[nt] += __shfl_xor_sync(0xFFFFFFFF, cp1[nt], 8);
                cp1[nt] += __shfl_xor_sync(0xFFFFFFFF, cp1[nt], 16);
            }
            if ((lane & 3) == 0) {
#pragma unroll
                for (int mt = 0; mt < 2; mt++) {
                    int r = wy * 32 + mt * 16 + (lane >> 2);
                    red_row[r * 4 + wx] = rlo[mt];
                    red_row[(r + 8) * 4 + wx] = rhi[mt];
                }
            }
            if (lane < 4) {
#pragma unroll
                for (int nt = 0; nt < 4; nt++) {
                    int c = wx * 32 + nt * 8 + lane * 2;
                    red_col[c * 4 + wy] = cp0[nt];
                    red_col[(c + 1) * 4 + wy] = cp1[nt];
                }
            }
        }
        if (pf) CP_WAIT0();
        __syncthreads();
        if (t > 0 && tid < 128) {
            float* red_row = (float*)(smem + RED_OFF + ((t - 1) & 1) * RED_PAR);
            float* red_col = red_row + 512;
            float rz = (red_row[tid * 4] + red_row[tid * 4 + 1]) +
                       (red_row[tid * 4 + 2] + red_row[tid * 4 + 3]);
            g_Zp[(size_t)(Ip * 128 + tid) * NT_ROW + Jp] = rz;
            if (!dtp) {
                float cz = (red_col[tid * 4] + red_col[tid * 4 + 1]) +
                           (red_col[tid * 4 + 2] + red_col[tid * 4 + 3]);
                g_Zp[(size_t)(Jp * 128 + tid) * NT_ROW + Ip] = cz;
            }
        }

        // carry tile t's accumulators as "previous"
#pragma unroll
        for (int mt = 0; mt < 2; mt++)
#pragma unroll
            for (int nt = 0; nt < 4; nt++)
#pragma unroll
                for (int q = 0; q < 4; q++) prev[mt][nt][q] = acc[mt][nt][q];
        Ip = I; Jp = J; dtp = (I == J);
        I = I1; J = J1;
        ready = pf;
    }

    // ---- final epilogue for the last tile ----
    {
        float rlo[2] = {0.f, 0.f}, rhi[2] = {0.f, 0.f};
        float cp0[4] = {0.f, 0.f, 0.f, 0.f}, cp1[4] = {0.f, 0.f, 0.f, 0.f};
#pragma unroll
        for (int ks = 0; ks < 8; ks++) {
            int mt = ks & 1, nt = ks >> 1;
            int lr = lrl0 + mt * 16;
            int lc = lcb0 + nt * 8;
            float v0 = (dtp && lc == lr)         ? EXP_DIAG : ex2f(prev[mt][nt][0] * EXP_SCALE);
            float v1 = (dtp && lc + 1 == lr)     ? EXP_DIAG : ex2f(prev[mt][nt][1] * EXP_SCALE);
            float v2 = (dtp && lc == lr + 8)     ? EXP_DIAG : ex2f(prev[mt][nt][2] * EXP_SCALE);
            float v3 = (dtp && lc + 1 == lr + 8) ? EXP_DIAG : ex2f(prev[mt][nt][3] * EXP_SCALE);
            rlo[mt] += v0 + v1;
            rhi[mt] += v2 + v3;
            cp0[nt] += v0 + v2;
            cp1[nt] += v1 + v3;
        }
        float* red_row = (float*)(smem + RED_OFF + ((cnt - 1) & 1) * RED_PAR);
        float* red_col = red_row + 512;
#pragma unroll
        for (int mt = 0; mt < 2; mt++) {
            rlo[mt] += __shfl_xor_sync(0xFFFFFFFF, rlo[mt], 1);
            rlo[mt] += __shfl_xor_sync(0xFFFFFFFF, rlo[mt], 2);
            rhi[mt] += __shfl_xor_sync(0xFFFFFFFF, rhi[mt], 1);
            rhi[mt] += __shfl_xor_sync(0xFFFFFFFF, rhi[mt], 2);
        }
#pragma unroll
        for (int nt = 0; nt < 4; nt++) {
            cp0[nt] += __shfl_xor_sync(0xFFFFFFFF, cp0[nt], 4);
            cp0[nt] += __shfl_xor_sync(0xFFFFFFFF, cp0[nt], 8);
            cp0[nt] += __shfl_xor_sync(0xFFFFFFFF, cp0[nt], 16);
            cp1[nt] += __shfl_xor_sync(0xFFFFFFFF, cp1[nt], 4);
            cp1[nt] += __shfl_xor_sync(0xFFFFFFFF, cp1[nt], 8);
            cp1[nt] += __shfl_xor_sync(0xFFFFFFFF, cp1[nt], 16);
        }
        if ((lane & 3) == 0) {
#pragma unroll
            for (int mt = 0; mt < 2; mt++) {
                int r = wy * 32 + mt * 16 + (lane >> 2);
                red_row[r * 4 + wx] = rlo[mt];
                red_row[(r + 8) * 4 + wx] = rhi[mt];
            }
        }
        if (lane < 4) {
#pragma unroll
            for (int nt = 0; nt < 4; nt++) {
                int c = wx * 32 + nt * 8 + lane * 2;
                red_col[c * 4 + wy] = cp0[nt];
                red_col[(c + 1) * 4 + wy] = cp1[nt];
            }
        }
        __syncthreads();
        if (tid < 128) {
            float rz = (red_row[tid * 4] + red_row[tid * 4 + 1]) +
                       (red_row[tid * 4 + 2] + red_row[tid * 4 + 3]);
            g_Zp[(size_t)(Ip * 128 + tid) * NT_ROW + Jp] = rz;
            if (!dtp) {
                float cz = (red_col[tid * 4] + red_col[tid * 4 + 1]) +
                           (red_col[tid * 4 + 2] + red_col[tid * 4 + 3]);
                g_Zp[(size_t)(Jp * 128 + tid) * NT_ROW + Ip] = cz;
            }
        }
    }
}

// ---------------- 5) per-row contrastive loss ---------------------------------------
__global__ void k_con(const int* __restrict__ tgt) {
    int w = threadIdx.x >> 5, lane = threadIdx.x & 31;
    int row = blockIdx.x * 8 + w;
    int t = tgt[row];
    float zs = g_Zp[(size_t)row * NT_ROW + lane] + g_Zp[(size_t)row * NT_ROW + lane + 32];
    const float4* e = (const float4*)&g_embn[(size_t)row * DIM];
    const float4* sc = (const float4*)&g_clsum[t * DIM];
    float dot = 0.f;
#pragma unroll
    for (int k = lane; k < DIM / 4; k += 32) {
        float4 a = e[k], b = sc[k];
        dot += a.x * b.x + a.y * b.y + a.z * b.z + a.w * b.w;
    }
#pragma unroll
    for (int off = 16; off > 0; off >>= 1) {
        dot += __shfl_xor_sync(0xFFFFFFFF, dot, off);
        zs += __shfl_xor_sync(0xFFFFFFFF, zs, off);
    }
    if (lane == 0) {
        float logZ = logf(zs + 1e-8f);
        float npos = g_clcnt[t] - 1.0f;
        float msum = (dot - 1.0f) * INV_T;
        g_con[row] = (npos * logZ - msum) / fmaxf(npos, 1.0f);
    }
}

// ---------------- 6) final reduction -------------------------------------------------
__global__ void k_final(float* __restrict__ out, int out_size) {
    __shared__ float s[256];
    int t = threadIdx.x;

    float cs = 0.f;
    for (int i = t; i < N; i += 256) cs += g_con[i];
    s[t] = cs;
    __syncthreads();
    for (int off = 128; off > 0; off >>= 1) {
        if (t < off) s[t] += s[t + off];
        __syncthreads();
    }
    __shared__ float con_sum;
    if (t == 0) con_sum = s[0];
    __syncthreads();

    s[t] = (t < 32) ? g_ce_part[t] : 0.f;
    __syncthreads();
    for (int off = 128; off > 0; off >>= 1) {
        if (t < off) s[t] += s[t + off];
        __syncthreads();
    }
    if (t == 0) {
        float ce_mean = s[0] * (1.0f / N);
        float con_mean = con_sum * (1.0f / N);
        out[0] = ce_mean + ALPHA * con_mean;
        if (out_size > 1) out[1] = ce_mean;
        if (out_size > 2) out[2] = con_mean;
    }
}

// ---------------- launcher ----------------------------------------------------------
extern "C" void kernel_launch(void* const* d_in, const int* in_sizes, int n_in,
                              void* d_out, int out_size) {
    const float* logits = (const float*)d_in[0];
    const float* emb = (const float*)d_in[1];
    const int* tgt = (const int*)d_in[2];
    float* out = (float*)d_out;

    cudaFuncSetAttribute(k_sim_sym, cudaFuncAttributeMaxDynamicSharedMemorySize, SMEM_TOTAL);

    k_norm<<<N / 8, 256>>>(emb);
    k_clspart<<<NCHUNK, 256>>>(tgt);
    k_clsfinal<<<CLS, DIM>>>();
    k_ce<<<N / 256, 256>>>(logits, tgt);
    k_sim_sym<<<148, 512, SMEM_TOTAL>>>();
    k_con<<<N / 8, 256>>>(tgt);
    k_final<<<1, 256>>>(out, out_size);
}

// round 9
// speedup vs baseline: 1.5123x; 1.0840x over previous
#include <cuda_runtime.h>
#include <math.h>
#include <stdint.h>

#define N 8192
#define CLS 8
#define DIM 256
#define INV_T 14.285714285714286f
#define EXP_SCALE 20.60992915555662f   /* (1/0.07) * log2(e) */
#define ALPHA 0.3f
#define LSM 0.1f
#define NT_ROW 64
#define NCHUNK 128                     /* class-sum chunks of 64 rows */

// ---------------- scratch ------------------------------------------------------------
__device__ float g_embn[N * DIM];
__device__ uint16_t g_embq[N * DIM / 2];
__device__ float g_clsum_part[NCHUNK * CLS * DIM];
__device__ float g_clcnt_part[NCHUNK * CLS];
__device__ float g_clsum[CLS * DIM];
__device__ float g_clcnt[CLS];
__device__ float g_Zp[N * NT_ROW];
__device__ float g_con[N];
__device__ float g_ce_part[16 * 16];

// ---------------- helpers ------------------------------------------------------------
__device__ __forceinline__ uint32_t smem_u32(const void* p) {
    uint32_t a;
    asm("{ .reg .u64 t; cvta.to.shared.u64 t, %1; cvt.u32.u64 %0, t; }" : "=r"(a) : "l"(p));
    return a;
}
__device__ __forceinline__ float ex2f(float x) {
    float y; asm("ex2.approx.f32 %0, %1;" : "=f"(y) : "f"(x)); return y;
}
__device__ __forceinline__ void cp16(uint32_t dst, const void* src) {
    asm volatile("cp.async.cg.shared.global [%0], [%1], 16;" :: "r"(dst), "l"(src));
}
#define CP_COMMIT() asm volatile("cp.async.commit_group;" ::: "memory")
#define CP_WAIT0()  asm volatile("cp.async.wait_group 0;" ::: "memory")

__device__ __forceinline__ void ldsm4(uint32_t& r0, uint32_t& r1, uint32_t& r2, uint32_t& r3,
                                      uint32_t addr) {
    asm volatile("ldmatrix.sync.aligned.m8n8.x4.shared.b16 {%0,%1,%2,%3}, [%4];"
                 : "=r"(r0), "=r"(r1), "=r"(r2), "=r"(r3) : "r"(addr));
}
__device__ __forceinline__ void mma_fp8(float* c, uint32_t a0, uint32_t a1, uint32_t a2,
                                        uint32_t a3, uint32_t b0, uint32_t b1) {
    asm volatile("mma.sync.aligned.m16n8k32.row.col.f32.e4m3.e4m3.f32 "
                 "{%0,%1,%2,%3}, {%4,%5,%6,%7}, {%8,%9}, {%0,%1,%2,%3};"
                 : "+f"(c[0]), "+f"(c[1]), "+f"(c[2]), "+f"(c[3])
                 : "r"(a0), "r"(a1), "r"(a2), "r"(a3), "r"(b0), "r"(b1));
}
__device__ __forceinline__ uint16_t f2e4m3x2(float hi, float lo) {
    uint16_t r;
    asm("cvt.rn.satfinite.e4m3x2.f32 %0, %1, %2;" : "=h"(r) : "f"(hi), "f"(lo));
    return r;
}

// ---------------- 1) normalize + fp8 convert (warp per row) --------------------------
__global__ void k_norm(const float* __restrict__ emb) {
    int w = threadIdx.x >> 5, lane = threadIdx.x & 31;
    int row = blockIdx.x * 8 + w;
    const float4* src = (const float4*)(emb + (size_t)row * DIM);
    float4 v0 = src[lane * 2], v1 = src[lane * 2 + 1];
    float ss = v0.x * v0.x + v0.y * v0.y + v0.z * v0.z + v0.w * v0.w +
               v1.x * v1.x + v1.y * v1.y + v1.z * v1.z + v1.w * v1.w;
#pragma unroll
    for (int off = 16; off > 0; off >>= 1) ss += __shfl_xor_sync(0xFFFFFFFF, ss, off);
    float norm = fmaxf(sqrtf(ss), 1e-12f);
    float inv = 1.0f / norm;
    v0.x *= inv; v0.y *= inv; v0.z *= inv; v0.w *= inv;
    v1.x *= inv; v1.y *= inv; v1.z *= inv; v1.w *= inv;
    float4* dst = (float4*)(g_embn + (size_t)row * DIM);
    dst[lane * 2] = v0;
    dst[lane * 2 + 1] = v1;
    uint32_t u0 = (uint32_t)f2e4m3x2(v0.y, v0.x) | ((uint32_t)f2e4m3x2(v0.w, v0.z) << 16);
    uint32_t u1 = (uint32_t)f2e4m3x2(v1.y, v1.x) | ((uint32_t)f2e4m3x2(v1.w, v1.z) << 16);
    *(uint2*)(g_embq + (size_t)row * 128 + lane * 4) = make_uint2(u0, u1);
}

// ---------------- 2b) class-sum final (128 chunks) -----------------------------------
__global__ void k_clsfinal() {
    int c = blockIdx.x, d = threadIdx.x;
    float s = 0.f;
    for (int b = 0; b < NCHUNK; b++) s += g_clsum_part[(b * CLS + c) * DIM + d];
    g_clsum[c * DIM + d] = s;
    if (d == 0) {
        float cn = 0.f;
        for (int b = 0; b < NCHUNK; b++) cn += g_clcnt_part[b * CLS + c];
        g_clcnt[c] = cn;
    }
}

// ---------------- 4) HOT: symmetric Z + folded side jobs -----------------------------
// 148 CTAs x 14/15 tiles (2080). 512 thr, 16 warps (4x4), warp tile 32x32.
// A and B both double-buffered; diagonal tiles read B from the A buffer.
// CTAs 8..71 also compute class-sum partials; CTAs 72..87 compute focal-CE partials
// (overlapped with initial tile loads; critical 15-tile CTAs bid<8 get no extra job).
#define SAB 272
#define A_BYTES (128 * SAB)              /* 34816 */
#define AS(p) ((p) * A_BYTES)
#define BS(b) ((2 + (b)) * A_BYTES)
#define RED_OFF (4 * A_BYTES)            /* 139264 */
#define RED_PAR 4096
#define SMEM_TOTAL (RED_OFF + 2 * RED_PAR)

__device__ __forceinline__ void load_tile_async(uint32_t sbase, int grow0, int tid) {
    const char* src = (const char*)g_embq + (size_t)grow0 * 256;
#pragma unroll
    for (int i = 0; i < 4; i++) {
        int idx = tid + i * 512;
        int row = idx >> 4, cb = idx & 15;
        cp16(sbase + row * SAB + cb * 16, src + (size_t)row * 256 + cb * 16);
    }
}

__global__ void __launch_bounds__(512, 1) k_sim_sym(const float* __restrict__ logits,
                                                   const int* __restrict__ tgt) {
    extern __shared__ char smem[];
    uint32_t sb = smem_u32(smem);
    int tid = threadIdx.x;
    int lane = tid & 31;
    int wid = tid >> 5;
    int wx = wid & 3;
    int wy = wid >> 2;
    int bid = blockIdx.x;

    int base = bid * 14 + (bid < 8 ? bid : 8);
    int cnt = 14 + (bid < 8 ? 1 : 0);

    int idx = base, I = 0;
    while (idx >= NT_ROW - I) { idx -= NT_ROW - I; I++; }
    int J = I + idx;

    // issue initial loads first (latency overlapped by side jobs below)
    int ap = 0;
    load_tile_async(sb + AS(0), I * 128, tid);
    if (J != I) load_tile_async(sb + BS(0), J * 128, tid);
    CP_COMMIT();

    // ---- folded side jobs ----
    if (bid >= 8 && bid < 72) {
        // class-sum partial: chunk = (bid-8)*2 + (tid>=256), 64 rows each
        int half = tid >> 8;
        int d = tid & 255;
        int chunk = (bid - 8) * 2 + half;
        int i0 = chunk * 64;
        float a[CLS];
#pragma unroll
        for (int c = 0; c < CLS; c++) a[c] = 0.f;
        for (int k = 0; k < 64; k++) {
            int tg = tgt[i0 + k];
            float v = g_embn[(size_t)(i0 + k) * DIM + d];
#pragma unroll
            for (int c = 0; c < CLS; c++) a[c] += (tg == c) ? v : 0.f;
        }
#pragma unroll
        for (int c = 0; c < CLS; c++) g_clsum_part[(chunk * CLS + c) * DIM + d] = a[c];
        if (d == 0) {
            int cc[CLS];
#pragma unroll
            for (int c = 0; c < CLS; c++) cc[c] = 0;
            for (int k = 0; k < 64; k++) {
                int tg = tgt[i0 + k];
#pragma unroll
                for (int c = 0; c < CLS; c++) cc[c] += (tg == c);
            }
#pragma unroll
            for (int c = 0; c < CLS; c++) g_clcnt_part[chunk * CLS + c] = (float)cc[c];
        }
    } else if (bid >= 72 && bid < 88) {
        // focal-CE partial: chunk = bid-72, 512 rows
        int chunk = bid - 72;
        int i = chunk * 512 + tid;
        const float4* p = (const float4*)(logits + (size_t)i * CLS);
        float4 u = p[0], w = p[1];
        float x[CLS] = {u.x, u.y, u.z, u.w, w.x, w.y, w.z, w.w};
        float m = x[0];
#pragma unroll
        for (int j = 1; j < CLS; j++) m = fmaxf(m, x[j]);
        float se = 0.f;
#pragma unroll
        for (int j = 0; j < CLS; j++) se += expf(x[j] - m);
        float lse = m + logf(se);
        int tg = tgt[i];
        float nll = lse - x[tg];
        float sx = 0.f;
#pragma unroll
        for (int j = 0; j < CLS; j++) sx += x[j];
        float smooth = lse - sx * (1.0f / CLS);
        float ce = (1.0f - LSM) * nll + LSM * smooth;
        float pt = expf(-ce);
        float omp = 1.0f - pt;
        float focal = omp * omp * ce;
#pragma unroll
        for (int off = 16; off > 0; off >>= 1)
            focal += __shfl_xor_sync(0xFFFFFFFF, focal, off);
        if (lane == 0) g_ce_part[chunk * 16 + wid] = focal;
    }

    CP_WAIT0();
    __syncthreads();

    uint32_t a_lane = (wy * 32 + (lane & 15)) * SAB + ((lane >> 4) << 4);
    uint32_t b_lane = ((lane & 7) + ((lane >> 4) << 3)) * SAB + (((lane >> 3) & 1) << 4) +
                      (wx * 32) * SAB;

    const float EXP_DIAG = expf(INV_T);
    int lrl0 = wy * 32 + (lane >> 2);
    int lcb0 = wx * 32 + (lane & 3) * 2;

    float prev[2][4][4];
    int Ip = 0, Jp = 0;
    bool dtp = false;

    for (int t = 0; t < cnt; t++) {
        int I1 = I, J1 = J + 1;
        if (J1 == NT_ROW) { I1 = I + 1; J1 = I1; }
        bool havenext = (t + 1 < cnt);
        int apn = ap;
        if (havenext) {
            if (I1 != I) {
                apn = ap ^ 1;
                load_tile_async(sb + AS(apn), I1 * 128, tid);
            }
            if (J1 != I1) {
                load_tile_async(sb + BS((t + 1) & 1), J1 * 128, tid);
            }
            CP_COMMIT();
        }

        bool dt = (I == J);
        uint32_t a_addr = sb + AS(ap) + a_lane;
        uint32_t bbuf = (dt ? (sb + AS(ap)) : (sb + BS(t & 1))) + b_lane;

        float acc[2][4][4];
#pragma unroll
        for (int mt = 0; mt < 2; mt++)
#pragma unroll
            for (int nt = 0; nt < 4; nt++)
#pragma unroll
                for (int q = 0; q < 4; q++) acc[mt][nt][q] = 0.f;

        float rlo[2] = {0.f, 0.f}, rhi[2] = {0.f, 0.f};
        float cp0[4] = {0.f, 0.f, 0.f, 0.f}, cp1[4] = {0.f, 0.f, 0.f, 0.f};

#pragma unroll
        for (int ks = 0; ks < 8; ks++) {
            uint32_t koff = ks * 32;
            uint32_t a0[4], a1[4];
            ldsm4(a0[0], a0[1], a0[2], a0[3], a_addr + koff);
            ldsm4(a1[0], a1[1], a1[2], a1[3], a_addr + 16 * SAB + koff);
            uint32_t bfr[2][4];
#pragma unroll
            for (int p = 0; p < 2; p++)
                ldsm4(bfr[p][0], bfr[p][1], bfr[p][2], bfr[p][3],
                      bbuf + (p * 16) * SAB + koff);
#pragma unroll
            for (int nt = 0; nt < 4; nt++) {
                uint32_t bb0 = bfr[nt >> 1][(nt & 1) * 2];
                uint32_t bb1 = bfr[nt >> 1][(nt & 1) * 2 + 1];
                mma_fp8(acc[0][nt], a0[0], a0[1], a0[2], a0[3], bb0, bb1);
                mma_fp8(acc[1][nt], a1[0], a1[1], a1[2], a1[3], bb0, bb1);
            }
            if (t > 0) {
                int mt = ks & 1, nt = ks >> 1;
                int lr = lrl0 + mt * 16;
                int lc = lcb0 + nt * 8;
                float v0 = (dtp && lc == lr)         ? EXP_DIAG : ex2f(prev[mt][nt][0] * EXP_SCALE);
                float v1 = (dtp && lc + 1 == lr)     ? EXP_DIAG : ex2f(prev[mt][nt][1] * EXP_SCALE);
                float v2 = (dtp && lc == lr + 8)     ? EXP_DIAG : ex2f(prev[mt][nt][2] * EXP_SCALE);
                float v3 = (dtp && lc + 1 == lr + 8) ? EXP_DIAG : ex2f(prev[mt][nt][3] * EXP_SCALE);
                rlo[mt] += v0 + v1;
                rhi[mt] += v2 + v3;
                cp0[nt] += v0 + v2;
                cp1[nt] += v1 + v3;
            }
        }

        if (t > 0) {
            float* red_row = (float*)(smem + RED_OFF + ((t - 1) & 1) * RED_PAR);
            float* red_col = red_row + 512;
#pragma unroll
            for (int mt = 0; mt < 2; mt++) {
                rlo[mt] += __shfl_xor_sync(0xFFFFFFFF, rlo[mt], 1);
                rlo[mt] += __shfl_xor_sync(0xFFFFFFFF, rlo[mt], 2);
                rhi[mt] += __shfl_xor_sync(0xFFFFFFFF, rhi[mt], 1);
                rhi[mt] += __shfl_xor_sync(0xFFFFFFFF, rhi[mt], 2);
            }
#pragma unroll
            for (int nt = 0; nt < 4; nt++) {
                cp0[nt] += __shfl_xor_sync(0xFFFFFFFF, cp0[nt], 4);
                cp0[nt] += __shfl_xor_sync(0xFFFFFFFF, cp0[nt], 8);
                cp0[nt] += __shfl_xor_sync(0xFFFFFFFF, cp0[nt], 16);
                cp1[nt] += __shfl_xor_sync(0xFFFFFFFF, cp1[nt], 4);
                cp1[nt] += __shfl_xor_sync(0xFFFFFFFF, cp1[nt], 8);
                cp1[nt] += __shfl_xor_sync(0xFFFFFFFF, cp1[nt], 16);
            }
            if ((lane & 3) == 0) {
#pragma unroll
                for (int mt = 0; mt < 2; mt++) {
                    int r = wy * 32 + mt * 16 + (lane >> 2);
                    red_row[r * 4 + wx] = rlo[mt];
                    red_row[(r + 8) * 4 + wx] = rhi[mt];
                }
            }
            if (lane < 4) {
#pragma unroll
                for (int nt = 0; nt < 4; nt++) {
                    int c = wx * 32 + nt * 8 + lane * 2;
                    red_col[c * 4 + wy] = cp0[nt];
                    red_col[(c + 1) * 4 + wy] = cp1[nt];
                }
            }
        }
        if (havenext) CP_WAIT0();
        __syncthreads();
        if (t > 0 && tid < 128) {
            float* red_row = (float*)(smem + RED_OFF + ((t - 1) & 1) * RED_PAR);
            float* red_col = red_row + 512;
            float rz = (red_row[tid * 4] + red_row[tid * 4 + 1]) +
                       (red_row[tid * 4 + 2] + red_row[tid * 4 + 3]);
            g_Zp[(size_t)(Ip * 128 + tid) * NT_ROW + Jp] = rz;
            if (!dtp) {
                float cz = (red_col[tid * 4] + red_col[tid * 4 + 1]) +
                           (red_col[tid * 4 + 2] + red_col[tid * 4 + 3]);
                g_Zp[(size_t)(Jp * 128 + tid) * NT_ROW + Ip] = cz;
            }
        }

#pragma unroll
        for (int mt = 0; mt < 2; mt++)
#pragma unroll
            for (int nt = 0; nt < 4; nt++)
#pragma unroll
                for (int q = 0; q < 4; q++) prev[mt][nt][q] = acc[mt][nt][q];
        Ip = I; Jp = J; dtp = (I == J);
        I = I1; J = J1; ap = apn;
    }

    // ---- final epilogue for the last tile ----
    {
        float rlo[2] = {0.f, 0.f}, rhi[2] = {0.f, 0.f};
        float cp0[4] = {0.f, 0.f, 0.f, 0.f}, cp1[4] = {0.f, 0.f, 0.f, 0.f};
#pragma unroll
        for (int ks = 0; ks < 8; ks++) {
            int mt = ks & 1, nt = ks >> 1;
            int lr = lrl0 + mt * 16;
            int lc = lcb0 + nt * 8;
            float v0 = (dtp && lc == lr)         ? EXP_DIAG : ex2f(prev[mt][nt][0] * EXP_SCALE);
            float v1 = (dtp && lc + 1 == lr)     ? EXP_DIAG : ex2f(prev[mt][nt][1] * EXP_SCALE);
            float v2 = (dtp && lc == lr + 8)     ? EXP_DIAG : ex2f(prev[mt][nt][2] * EXP_SCALE);
            float v3 = (dtp && lc + 1 == lr + 8) ? EXP_DIAG : ex2f(prev[mt][nt][3] * EXP_SCALE);
            rlo[mt] += v0 + v1;
            rhi[mt] += v2 + v3;
            cp0[nt] += v0 + v2;
            cp1[nt] += v1 + v3;
        }
        float* red_row = (float*)(smem + RED_OFF + ((cnt - 1) & 1) * RED_PAR);
        float* red_col = red_row + 512;
#pragma unroll
        for (int mt = 0; mt < 2; mt++) {
            rlo[mt] += __shfl_xor_sync(0xFFFFFFFF, rlo[mt], 1);
            rlo[mt] += __shfl_xor_sync(0xFFFFFFFF, rlo[mt], 2);
            rhi[mt] += __shfl_xor_sync(0xFFFFFFFF, rhi[mt], 1);
            rhi[mt] += __shfl_xor_sync(0xFFFFFFFF, rhi[mt], 2);
        }
#pragma unroll
        for (int nt = 0; nt < 4; nt++) {
            cp0[nt] += __shfl_xor_sync(0xFFFFFFFF, cp0[nt], 4);
            cp0[nt] += __shfl_xor_sync(0xFFFFFFFF, cp0[nt], 8);
            cp0[nt] += __shfl_xor_sync(0xFFFFFFFF, cp0[nt], 16);
            cp1[nt] += __shfl_xor_sync(0xFFFFFFFF, cp1[nt], 4);
            cp1[nt] += __shfl_xor_sync(0xFFFFFFFF, cp1[nt], 8);
            cp1[nt] += __shfl_xor_sync(0xFFFFFFFF, cp1[nt], 16);
        }
        if ((lane & 3) == 0) {
#pragma unroll
            for (int mt = 0; mt < 2; mt++) {
                int r = wy * 32 + mt * 16 + (lane >> 2);
                red_row[r * 4 + wx] = rlo[mt];
                red_row[(r + 8) * 4 + wx] = rhi[mt];
            }
        }
        if (lane < 4) {
#pragma unroll
            for (int nt = 0; nt < 4; nt++) {
                int c = wx * 32 + nt * 8 + lane * 2;
                red_col[c * 4 + wy] = cp0[nt];
                red_col[(c + 1) * 4 + wy] = cp1[nt];
            }
        }
        __syncthreads();
        if (tid < 128) {
            float rz = (red_row[tid * 4] + red_row[tid * 4 + 1]) +
                       (red_row[tid * 4 + 2] + red_row[tid * 4 + 3]);
            g_Zp[(size_t)(Ip * 128 + tid) * NT_ROW + Jp] = rz;
            if (!dtp) {
                float cz = (red_col[tid * 4] + red_col[tid * 4 + 1]) +
                           (red_col[tid * 4 + 2] + red_col[tid * 4 + 3]);
                g_Zp[(size_t)(Jp * 128 + tid) * NT_ROW + Ip] = cz;
            }
        }
    }
}

// ---------------- 5) per-row contrastive loss ---------------------------------------
__global__ void k_con(const int* __restrict__ tgt) {
    int w = threadIdx.x >> 5, lane = threadIdx.x & 31;
    int row = blockIdx.x * 8 + w;
    int t = tgt[row];
    float zs = g_Zp[(size_t)row * NT_ROW + lane] + g_Zp[(size_t)row * NT_ROW + lane + 32];
    const float4* e = (const float4*)&g_embn[(size_t)row * DIM];
    const float4* sc = (const float4*)&g_clsum[t * DIM];
    float dot = 0.f;
#pragma unroll
    for (int k = lane; k < DIM / 4; k += 32) {
        float4 a = e[k], b = sc[k];
        dot += a.x * b.x + a.y * b.y + a.z * b.z + a.w * b.w;
    }
#pragma unroll
    for (int off = 16; off > 0; off >>= 1) {
        dot += __shfl_xor_sync(0xFFFFFFFF, dot, off);
        zs += __shfl_xor_sync(0xFFFFFFFF, zs, off);
    }
    if (lane == 0) {
        float logZ = logf(zs + 1e-8f);
        float npos = g_clcnt[t] - 1.0f;
        float msum = (dot - 1.0f) * INV_T;
        g_con[row] = (npos * logZ - msum) / fmaxf(npos, 1.0f);
    }
}

// ---------------- 6) final reduction -------------------------------------------------
__global__ void k_final(float* __restrict__ out, int out_size) {
    __shared__ float s[256];
    int t = threadIdx.x;

    float cs = 0.f;
    for (int i = t; i < N; i += 256) cs += g_con[i];
    s[t] = cs;
    __syncthreads();
    for (int off = 128; off > 0; off >>= 1) {
        if (t < off) s[t] += s[t + off];
        __syncthreads();
    }
    __shared__ float con_sum;
    if (t == 0) con_sum = s[0];
    __syncthreads();

    s[t] = g_ce_part[t];
    __syncthreads();
    for (int off = 128; off > 0; off >>= 1) {
        if (t < off) s[t] += s[t + off];
        __syncthreads();
    }
    if (t == 0) {
        float ce_mean = s[0] * (1.0f / N);
        float con_mean = con_sum * (1.0f / N);
        out[0] = ce_mean + ALPHA * con_mean;
        if (out_size > 1) out[1] = ce_mean;
        if (out_size > 2) out[2] = con_mean;
    }
}

// ---------------- launcher ----------------------------------------------------------
extern "C" void kernel_launch(void* const* d_in, const int* in_sizes, int n_in,
                              void* d_out, int out_size) {
    const float* logits = (const float*)d_in[0];
    const float* emb = (const float*)d_in[1];
    const int* tgt = (const int*)d_in[2];
    float* out = (float*)d_out;

    cudaFuncSetAttribute(k_sim_sym, cudaFuncAttributeMaxDynamicSharedMemorySize, SMEM_TOTAL);

    k_norm<<<N / 8, 256>>>(emb);
    k_sim_sym<<<148, 512, SMEM_TOTAL>>>(logits, tgt);
    k_clsfinal<<<CLS, DIM>>>();
    k_con<<<N / 8, 256>>>(tgt);
    k_final<<<1, 256>>>(out, out_size);
}